// round 10
// baseline (speedup 1.0000x reference)
#include <cuda_runtime.h>
#include <cstdint>

#define DD 128
#define ROWS_ITER 256        // rows per CTA iteration (16 per warp)
#define ITERS 4              // iterations per CTA -> 1024 rows/CTA
#define NTHREADS 512

// ---- smem byte offsets ----
#define SM_B1HI  0           // R hi tf32, k8-frag packed (GEMM1 B; remapped for GEMM2 tf32)
#define SM_BH16  65536       // R hi bf16, k16-frag packed (GEMM1)
#define SM_BL16  98304       // R lo bf16, k16-frag packed (GEMM1)
#define SM_B2H16 131072      // R^T hi bf16, k16-frag packed (GEMM2)
#define SM_ZI    163840      // indices: 256 rows x 132 bytes
#define SM_NRM   197632
#define SM_INV   198656
#define SM_SCL   199680
#define SM_ISCL  200192
#define SMEM_BYTES 200704

__device__ __forceinline__ uint32_t tf32u(float x) {
    uint32_t r;
    asm("cvt.rna.tf32.f32 %0, %1;" : "=r"(r) : "f"(x));
    return r;
}
__device__ __forceinline__ float tf32f(float x) { return __uint_as_float(tf32u(x)); }

// pack {hi_elem, lo_elem} into bf16x2 (hi -> upper 16 bits)
__device__ __forceinline__ uint32_t bfpack(float hi, float lo) {
    uint32_t r;
    asm("cvt.rn.bf16x2.f32 %0, %1, %2;" : "=r"(r) : "f"(hi), "f"(lo));
    return r;
}

__device__ __forceinline__ void mma8(float d[4], const uint32_t a[4],
                                     uint32_t b0, uint32_t b1) {
    asm volatile(
        "mma.sync.aligned.m16n8k8.row.col.f32.tf32.tf32.f32 "
        "{%0,%1,%2,%3}, {%4,%5,%6,%7}, {%8,%9}, {%0,%1,%2,%3};"
        : "+f"(d[0]), "+f"(d[1]), "+f"(d[2]), "+f"(d[3])
        : "r"(a[0]), "r"(a[1]), "r"(a[2]), "r"(a[3]), "r"(b0), "r"(b1));
}
__device__ __forceinline__ void mma16bf(float d[4], const uint32_t a[4],
                                        uint32_t b0, uint32_t b1) {
    asm volatile(
        "mma.sync.aligned.m16n8k16.row.col.f32.bf16.bf16.f32 "
        "{%0,%1,%2,%3}, {%4,%5,%6,%7}, {%8,%9}, {%0,%1,%2,%3};"
        : "+f"(d[0]), "+f"(d[1]), "+f"(d[2]), "+f"(d[3])
        : "r"(a[0]), "r"(a[1]), "r"(a[2]), "r"(a[3]), "r"(b0), "r"(b1));
}

extern "C" __global__ void __launch_bounds__(NTHREADS, 1)
rotadapt_mma_kernel(const float* __restrict__ k,
                    const float* __restrict__ rot,
                    const float* __restrict__ scales,
                    const float* __restrict__ cent,
                    float* __restrict__ out)
{
    extern __shared__ char sb[];
    float* sclp  = (float*)(sb + SM_SCL);
    float* isclp = (float*)(sb + SM_ISCL);
    float* nrmp  = (float*)(sb + SM_NRM);
    float* invp  = (float*)(sb + SM_INV);

    const int tid  = threadIdx.x;
    const int lane = tid & 31, w = tid >> 5;      // 16 warps
    const int g = lane >> 2, t = lane & 3;
    const int rA = 16 * w + g;                    // warp owns rows [16w, 16w+16)

    // ---- prologue 1: R -> tf32-hi k8-frag table ----
    for (int idx = tid; idx < DD * DD; idx += NTHREADS) {
        int j = idx >> 7, i = idx & 127;
        float v = rot[idx];
        int fi = (((i >> 3) * 16 + (j >> 3)) * 32 + (j & 7) * 4 + (i & 3)) * 2
                 + ((i >> 2) & 1);
        ((uint32_t*)(sb + SM_B1HI))[fi] = tf32u(v);
    }
    // ---- prologue 2: bf16 k16-frag tables (GEMM1 hi/lo + GEMM2 hi) ----
    {
        uint32_t* bh16  = (uint32_t*)(sb + SM_BH16);
        uint32_t* bl16  = (uint32_t*)(sb + SM_BL16);
        uint32_t* b2h16 = (uint32_t*)(sb + SM_B2H16);
        for (int u = tid; u < 8 * 16 * 32; u += NTHREADS) {
            int ln = u & 31, nt = (u >> 5) & 15, ks = u >> 9;
            int gg = ln >> 2, t2 = ln & 3;
            int n = 8 * nt + gg;
            int k0c = 16 * ks + 2 * t2;
            // GEMM1: B[kk][n] = R[n][kk]
            float r0 = rot[n * DD + k0c],     r1 = rot[n * DD + k0c + 1];
            float r2 = rot[n * DD + k0c + 8], r3 = rot[n * DD + k0c + 9];
            float h0 = tf32f(r0), h1 = tf32f(r1), h2 = tf32f(r2), h3 = tf32f(r3);
            bh16[u * 2]     = bfpack(h1, h0);
            bh16[u * 2 + 1] = bfpack(h3, h2);
            bl16[u * 2]     = bfpack(r1 - h1, r0 - h0);
            bl16[u * 2 + 1] = bfpack(r3 - h3, r2 - h2);
            // GEMM2: B2[kk][n] = R[kk][n]
            float s0 = rot[k0c * DD + n],       s1 = rot[(k0c + 1) * DD + n];
            float s2 = rot[(k0c + 8) * DD + n], s3 = rot[(k0c + 9) * DD + n];
            b2h16[u * 2]     = bfpack(tf32f(s1), tf32f(s0));
            b2h16[u * 2 + 1] = bfpack(tf32f(s3), tf32f(s2));
        }
    }
    if (tid < DD) {
        float s = scales[tid];
        sclp[tid]  = s;
        isclp[tid] = 1.0f / fmaxf(s, 1e-6f);
    }

    float bn[7];
    #pragma unroll
    for (int q = 0; q < 7; ++q) bn[q] = 0.5f * (cent[q] + cent[q + 1]);
    const float ccv = cent[lane & 7];

    __syncthreads();   // the ONLY block barrier: B tables + scales ready

    const float2*    bh2   = (const float2*)(sb + SM_B1HI);
    const float*     bhf   = (const float*)(sb + SM_B1HI);
    const uint2*     bh16v = (const uint2*)(sb + SM_BH16);
    const uint2*     bl16v = (const uint2*)(sb + SM_BL16);
    const uint2*     b2h16v= (const uint2*)(sb + SM_B2H16);
    char* zi = sb + SM_ZI;

    const long ctabase = (long)blockIdx.x * (ROWS_ITER * ITERS);

    for (int tt = 0; tt < ITERS; ++tt) {
        const long rowbase = ctabase + (long)tt * ROWS_ITER;

        // ---- phase A: row norms (warp-private rows) ----
        {
            const int sub = lane >> 3, c8 = lane & 7;
            #pragma unroll
            for (int p = 0; p < 4; ++p) {
                int row = 16 * w + 4 * p + sub;
                const float4* kp = (const float4*)(k + (rowbase + row) * (long)DD);
                float ssq = 0.0f;
                #pragma unroll
                for (int ci = 0; ci < 4; ++ci) {
                    float4 v = kp[ci * 8 + c8];
                    ssq += v.x * v.x + v.y * v.y + v.z * v.z + v.w * v.w;
                }
                ssq += __shfl_xor_sync(0xffffffffu, ssq, 1);
                ssq += __shfl_xor_sync(0xffffffffu, ssq, 2);
                ssq += __shfl_xor_sync(0xffffffffu, ssq, 4);
                if (c8 == 0) {
                    float nr = sqrtf(ssq);
                    nrmp[row] = nr;
                    invp[row] = 1.0f / (nr + 1e-10f);
                }
            }
        }
        __syncwarp();
        const float inv0 = invp[rA], inv1 = invp[rA + 8];
        const float nrm0 = nrmp[rA], nrm1 = nrmp[rA + 8];

        // ---- GEMM1: tf32 hi (2x k8) + bf16 corrections (k16) ----
        float acc[16][4];
        #pragma unroll
        for (int nt = 0; nt < 16; ++nt)
            #pragma unroll
            for (int p = 0; p < 4; ++p) acc[nt][p] = 0.0f;

        {
            const float* k0 = k + (rowbase + rA) * (long)DD;
            const float* k1 = k0 + 8 * DD;

            #pragma unroll 2
            for (int ks16 = 0; ks16 < 8; ++ks16) {
                // tf32 A frags for the two k8 sub-steps
                uint32_t ah0[4], ah1[4];
                {
                    int o0 = 16 * ks16 + t, o1 = o0 + 8;
                    ah0[0] = tf32u(k0[o0] * inv0);     ah0[1] = tf32u(k1[o0] * inv1);
                    ah0[2] = tf32u(k0[o0 + 4] * inv0); ah0[3] = tf32u(k1[o0 + 4] * inv1);
                    ah1[0] = tf32u(k0[o1] * inv0);     ah1[1] = tf32u(k1[o1] * inv1);
                    ah1[2] = tf32u(k0[o1 + 4] * inv0); ah1[3] = tf32u(k1[o1 + 4] * inv1);
                }
                // bf16 A frags (different column set: 2t,2t+1,+8,+9)
                uint32_t alf[4], ahf[4];
                {
                    int c0 = 16 * ks16 + 2 * t;
                    float v00 = k0[c0] * inv0,     v01 = k0[c0 + 1] * inv0;
                    float v10 = k1[c0] * inv1,     v11 = k1[c0 + 1] * inv1;
                    float v02 = k0[c0 + 8] * inv0, v03 = k0[c0 + 9] * inv0;
                    float v12 = k1[c0 + 8] * inv1, v13 = k1[c0 + 9] * inv1;
                    float h00 = tf32f(v00), h01 = tf32f(v01), h10 = tf32f(v10), h11 = tf32f(v11);
                    float h02 = tf32f(v02), h03 = tf32f(v03), h12 = tf32f(v12), h13 = tf32f(v13);
                    alf[0] = bfpack(v01 - h01, v00 - h00);
                    alf[1] = bfpack(v11 - h11, v10 - h10);
                    alf[2] = bfpack(v03 - h03, v02 - h02);
                    alf[3] = bfpack(v13 - h13, v12 - h12);
                    ahf[0] = bfpack(h01, h00);
                    ahf[1] = bfpack(h11, h10);
                    ahf[2] = bfpack(h03, h02);
                    ahf[3] = bfpack(h13, h12);
                }
                #pragma unroll
                for (int grp = 0; grp < 4; ++grp) {
                    float2 bt0[4], bt1[4];
                    uint2 bbh[4], bbl[4];
                    #pragma unroll
                    for (int j = 0; j < 4; ++j) {
                        int nt = grp * 4 + j;
                        bt0[j] = bh2[((2 * ks16) * 16 + nt) * 32 + lane];
                        bt1[j] = bh2[((2 * ks16 + 1) * 16 + nt) * 32 + lane];
                        bbh[j] = bh16v[(ks16 * 16 + nt) * 32 + lane];
                        bbl[j] = bl16v[(ks16 * 16 + nt) * 32 + lane];
                    }
                    #pragma unroll
                    for (int j = 0; j < 4; ++j) {
                        int nt = grp * 4 + j;
                        mma8(acc[nt], ah0, __float_as_uint(bt0[j].x), __float_as_uint(bt0[j].y));
                        mma8(acc[nt], ah1, __float_as_uint(bt1[j].x), __float_as_uint(bt1[j].y));
                        mma16bf(acc[nt], alf, bbh[j].x, bbh[j].y);
                        mma16bf(acc[nt], ahf, bbl[j].x, bbl[j].y);
                    }
                }
            }
        }

        // ---- prefetch next iteration's k toward L2 ----
        if (tt + 1 < ITERS) {
            const char* np = (const char*)(k + (rowbase + ROWS_ITER) * (long)DD);
            #pragma unroll
            for (int pf = 0; pf < 2; ++pf)
                asm volatile("prefetch.global.L2 [%0];"
                             :: "l"(np + (pf * NTHREADS + tid) * 128));
        }

        // ---- epilogue 1: scale -> bucketize -> 8-bit indices to smem ----
        {
            const float2* scl2 = (const float2*)(sb + SM_SCL);
            #pragma unroll
            for (int nt = 0; nt < 16; ++nt) {
                float2 sc = scl2[(8 * nt + 2 * t) >> 1];
                float f0 = acc[nt][0] * sc.x, f1 = acc[nt][1] * sc.y;
                float f2 = acc[nt][2] * sc.x, f3 = acc[nt][3] * sc.y;
                int i0 = 0, i1 = 0, i2 = 0, i3 = 0;
                #pragma unroll
                for (int q = 0; q < 7; ++q) {
                    i0 += (f0 > bn[q]); i1 += (f1 > bn[q]);
                    i2 += (f2 > bn[q]); i3 += (f3 > bn[q]);
                }
                *(uint16_t*)(zi + rA * 132 + 8 * nt + 2 * t)       = (uint16_t)(i0 | (i1 << 8));
                *(uint16_t*)(zi + (rA + 8) * 132 + 8 * nt + 2 * t) = (uint16_t)(i2 | (i3 << 8));
            }
        }
        __syncwarp();

        // ---- GEMM2: tf32 zh (2x k8, B remapped from B1HI) + bf16 zl (k16) ----
        #pragma unroll
        for (int nt = 0; nt < 16; ++nt)
            #pragma unroll
            for (int p = 0; p < 4; ++p) acc[nt][p] = 0.0f;

        {
            const char* ziA = zi + rA * 132;
            const char* ziB = zi + (rA + 8) * 132;
            #pragma unroll 2
            for (int ks16 = 0; ks16 < 8; ++ks16) {
                const int k8a = 2 * ks16, k8b = k8a + 1;
                const int sh = 8 * t;
                uint32_t zh0[4], zh1[4], zlf[4];
                {
                    float isa0 = isclp[8 * k8a + t], isa1 = isclp[8 * k8a + t + 4];
                    uint32_t wa = *(const uint32_t*)(ziA + 8 * k8a);
                    uint32_t wb = *(const uint32_t*)(ziA + 8 * k8a + 4);
                    uint32_t wc = *(const uint32_t*)(ziB + 8 * k8a);
                    uint32_t wd = *(const uint32_t*)(ziB + 8 * k8a + 4);
                    zh0[0] = tf32u(__shfl_sync(0xffffffffu, ccv, (wa >> sh) & 0xff) * isa0);
                    zh0[1] = tf32u(__shfl_sync(0xffffffffu, ccv, (wc >> sh) & 0xff) * isa0);
                    zh0[2] = tf32u(__shfl_sync(0xffffffffu, ccv, (wb >> sh) & 0xff) * isa1);
                    zh0[3] = tf32u(__shfl_sync(0xffffffffu, ccv, (wd >> sh) & 0xff) * isa1);
                }
                {
                    float isb0 = isclp[8 * k8b + t], isb1 = isclp[8 * k8b + t + 4];
                    uint32_t wa = *(const uint32_t*)(ziA + 8 * k8b);
                    uint32_t wb = *(const uint32_t*)(ziA + 8 * k8b + 4);
                    uint32_t wc = *(const uint32_t*)(ziB + 8 * k8b);
                    uint32_t wd = *(const uint32_t*)(ziB + 8 * k8b + 4);
                    zh1[0] = tf32u(__shfl_sync(0xffffffffu, ccv, (wa >> sh) & 0xff) * isb0);
                    zh1[1] = tf32u(__shfl_sync(0xffffffffu, ccv, (wc >> sh) & 0xff) * isb0);
                    zh1[2] = tf32u(__shfl_sync(0xffffffffu, ccv, (wb >> sh) & 0xff) * isb1);
                    zh1[3] = tf32u(__shfl_sync(0xffffffffu, ccv, (wd >> sh) & 0xff) * isb1);
                }
                {
                    int c0 = 16 * ks16 + 2 * t;
                    float2 isc01 = *(const float2*)&isclp[c0];
                    float2 isc89 = *(const float2*)&isclp[c0 + 8];
                    uint32_t p0 = *(const uint16_t*)(ziA + c0);
                    uint32_t p1 = *(const uint16_t*)(ziB + c0);
                    uint32_t p2 = *(const uint16_t*)(ziA + c0 + 8);
                    uint32_t p3 = *(const uint16_t*)(ziB + c0 + 8);
                    float z00 = __shfl_sync(0xffffffffu, ccv, p0 & 0xff) * isc01.x;
                    float z01 = __shfl_sync(0xffffffffu, ccv, p0 >> 8)   * isc01.y;
                    float z10 = __shfl_sync(0xffffffffu, ccv, p1 & 0xff) * isc01.x;
                    float z11 = __shfl_sync(0xffffffffu, ccv, p1 >> 8)   * isc01.y;
                    float z02 = __shfl_sync(0xffffffffu, ccv, p2 & 0xff) * isc89.x;
                    float z03 = __shfl_sync(0xffffffffu, ccv, p2 >> 8)   * isc89.y;
                    float z12 = __shfl_sync(0xffffffffu, ccv, p3 & 0xff) * isc89.x;
                    float z13 = __shfl_sync(0xffffffffu, ccv, p3 >> 8)   * isc89.y;
                    zlf[0] = bfpack(z01 - tf32f(z01), z00 - tf32f(z00));
                    zlf[1] = bfpack(z11 - tf32f(z11), z10 - tf32f(z10));
                    zlf[2] = bfpack(z03 - tf32f(z03), z02 - tf32f(z02));
                    zlf[3] = bfpack(z13 - tf32f(z13), z12 - tf32f(z12));
                }
                #pragma unroll
                for (int grp = 0; grp < 4; ++grp) {
                    float b0a[4], b1a[4], b0b[4], b1b[4];
                    uint2 bb2[4];
                    #pragma unroll
                    for (int j = 0; j < 4; ++j) {
                        int nt = grp * 4 + j;
                        int basea = ((nt * 16 + k8a) * 32 + t * 4 + (g & 3)) * 2 + (g >> 2);
                        int baseb = ((nt * 16 + k8b) * 32 + t * 4 + (g & 3)) * 2 + (g >> 2);
                        b0a[j] = bhf[basea];
                        b1a[j] = bhf[basea + 32];
                        b0b[j] = bhf[baseb];
                        b1b[j] = bhf[baseb + 32];
                        bb2[j] = b2h16v[(ks16 * 16 + nt) * 32 + lane];
                    }
                    #pragma unroll
                    for (int j = 0; j < 4; ++j) {
                        int nt = grp * 4 + j;
                        mma8(acc[nt], zh0, __float_as_uint(b0a[j]), __float_as_uint(b1a[j]));
                        mma8(acc[nt], zh1, __float_as_uint(b0b[j]), __float_as_uint(b1b[j]));
                        mma16bf(acc[nt], zlf, bb2[j].x, bb2[j].y);
                    }
                }
            }
        }

        // ---- epilogue 2: x norm, store ----
        {
            float* o0 = out + (rowbase + rA) * (long)DD;
            float* o1 = o0 + 8 * DD;
            #pragma unroll
            for (int nt = 0; nt < 16; ++nt) {
                int c = 8 * nt + 2 * t;
                *(float2*)(o0 + c) = make_float2(acc[nt][0] * nrm0, acc[nt][1] * nrm0);
                *(float2*)(o1 + c) = make_float2(acc[nt][2] * nrm1, acc[nt][3] * nrm1);
            }
        }
    }
}

extern "C" void kernel_launch(void* const* d_in, const int* in_sizes, int n_in,
                              void* d_out, int out_size) {
    const float* k      = (const float*)d_in[0];
    const float* rot    = (const float*)d_in[1];
    const float* scales = (const float*)d_in[2];
    const float* cent   = (const float*)d_in[3];
    float* out = (float*)d_out;

    int nrows = in_sizes[0] / DD;
    int nblocks = nrows / (ROWS_ITER * ITERS);   // 1048576 / 1024 = 1024

    cudaFuncSetAttribute(rotadapt_mma_kernel,
                         cudaFuncAttributeMaxDynamicSharedMemorySize, SMEM_BYTES);
    rotadapt_mma_kernel<<<nblocks, NTHREADS, SMEM_BYTES>>>(k, rot, scales, cent, out);
}

// round 11
// speedup vs baseline: 1.1488x; 1.1488x over previous
#include <cuda_runtime.h>
#include <cstdint>

#define DD 128
#define ROWS_ITER 256        // rows per CTA iteration (16 per warp)
#define ITERS 4              // iterations per CTA -> 1024 rows/CTA
#define NTHREADS 512

// ---- smem byte offsets ----
#define SM_B1HI 0            // R hi, fragment-packed
#define SM_B1LO 65536        // R lo
#define SM_ZI   131072       // indices: 256 rows x 132 bytes
#define SM_SCL  164864       // 128 f32
#define SM_ISCL 165376       // 128 f32
#define SMEM_BYTES 165888

__device__ __forceinline__ uint32_t tf32u(float x) {
    uint32_t r;
    asm("cvt.rna.tf32.f32 %0, %1;" : "=r"(r) : "f"(x));
    return r;
}

__device__ __forceinline__ void mma8(float d[4], const uint32_t a[4],
                                     uint32_t b0, uint32_t b1) {
    asm volatile(
        "mma.sync.aligned.m16n8k8.row.col.f32.tf32.tf32.f32 "
        "{%0,%1,%2,%3}, {%4,%5,%6,%7}, {%8,%9}, {%0,%1,%2,%3};"
        : "+f"(d[0]), "+f"(d[1]), "+f"(d[2]), "+f"(d[3])
        : "r"(a[0]), "r"(a[1]), "r"(a[2]), "r"(a[3]), "r"(b0), "r"(b1));
}

__device__ __forceinline__ void split4(const float f[4], uint32_t h[4], uint32_t l[4]) {
    #pragma unroll
    for (int i = 0; i < 4; ++i) {
        h[i] = tf32u(f[i]);
        l[i] = tf32u(f[i] - __uint_as_float(h[i]));
    }
}

extern "C" __global__ void __launch_bounds__(NTHREADS, 1)
rotadapt_mma_kernel(const float* __restrict__ k,
                    const float* __restrict__ rot,
                    const float* __restrict__ scales,
                    const float* __restrict__ cent,
                    float* __restrict__ out)
{
    extern __shared__ char sb[];
    float* sclp  = (float*)(sb + SM_SCL);
    float* isclp = (float*)(sb + SM_ISCL);

    const int tid  = threadIdx.x;
    const int lane = tid & 31, w = tid >> 5;      // 16 warps
    const int g = lane >> 2, t = lane & 3;
    const int rA = 16 * w + g;                    // warp owns rows [16w, 16w+16)

    // ---- prologue: pack R into hi/lo fragment layout ----
    for (int idx = tid; idx < DD * DD; idx += NTHREADS) {
        int j = idx >> 7, i = idx & 127;
        float v = rot[idx];
        uint32_t hu = tf32u(v);
        uint32_t lu = tf32u(v - __uint_as_float(hu));
        int fi = (((i >> 3) * 16 + (j >> 3)) * 32 + (j & 7) * 4 + (i & 3)) * 2
                 + ((i >> 2) & 1);
        ((uint32_t*)(sb + SM_B1HI))[fi] = hu;
        ((uint32_t*)(sb + SM_B1LO))[fi] = lu;
    }
    if (tid < DD) {
        float s = scales[tid];
        sclp[tid]  = s;
        isclp[tid] = 1.0f / fmaxf(s, 1e-6f);
    }

    float bn[7];
    #pragma unroll
    for (int q = 0; q < 7; ++q) bn[q] = 0.5f * (cent[q] + cent[q + 1]);
    const float ccv = cent[lane & 7];

    __syncthreads();   // the ONLY block barrier: B tables + scales ready

    const float2* bh2 = (const float2*)(sb + SM_B1HI);
    const float2* bl2 = (const float2*)(sb + SM_B1LO);
    const float*  bhf = (const float*)(sb + SM_B1HI);
    char* zi = sb + SM_ZI;

    const long ctabase = (long)blockIdx.x * (ROWS_ITER * ITERS);

    for (int tt = 0; tt < ITERS; ++tt) {
        const long rowbase = ctabase + (long)tt * ROWS_ITER;

        // ---- GEMM1 (3-pass tf32) on RAW k: acc = k @ R^T (unnormalized) ----
        float acc[16][4];
        #pragma unroll
        for (int nt = 0; nt < 16; ++nt)
            #pragma unroll
            for (int p = 0; p < 4; ++p) acc[nt][p] = 0.0f;

        {
            const float* k0 = k + (rowbase + rA) * (long)DD;
            const float* k1 = k0 + 8 * DD;

            #pragma unroll 2
            for (int ks = 0; ks < 16; ++ks) {
                int o = 8 * ks + t;
                float fA[4] = { k0[o], k1[o], k0[o + 4], k1[o + 4] };
                uint32_t ah[4], al[4];
                split4(fA, ah, al);

                float2 bhb[2][4], blb[2][4];
                #pragma unroll
                for (int j = 0; j < 4; ++j) {
                    int fi = (ks * 16 + j) * 32 + lane;
                    bhb[0][j] = bh2[fi];
                    blb[0][j] = bl2[fi];
                }
                #pragma unroll
                for (int grp = 0; grp < 4; ++grp) {
                    const int cur = grp & 1, nxt = cur ^ 1;
                    if (grp < 3) {
                        #pragma unroll
                        for (int j = 0; j < 4; ++j) {
                            int fi = (ks * 16 + (grp + 1) * 4 + j) * 32 + lane;
                            bhb[nxt][j] = bh2[fi];
                            blb[nxt][j] = bl2[fi];
                        }
                    }
                    #pragma unroll
                    for (int j = 0; j < 4; ++j) {
                        int nt = grp * 4 + j;
                        uint32_t bh0 = __float_as_uint(bhb[cur][j].x);
                        uint32_t bh1 = __float_as_uint(bhb[cur][j].y);
                        uint32_t bl0 = __float_as_uint(blb[cur][j].x);
                        uint32_t bl1 = __float_as_uint(blb[cur][j].y);
                        mma8(acc[nt], ah, bh0, bh1);
                        mma8(acc[nt], al, bh0, bh1);
                        mma8(acc[nt], ah, bl0, bl1);
                    }
                }
            }
        }

        // ---- norms from acc: R orthogonal => ||k @ R^T|| = ||k|| ----
        float nrm0, nrm1, inv0, inv1;
        {
            float ssq0 = 0.0f, ssq1 = 0.0f;
            #pragma unroll
            for (int nt = 0; nt < 16; ++nt) {
                ssq0 += acc[nt][0] * acc[nt][0] + acc[nt][1] * acc[nt][1];
                ssq1 += acc[nt][2] * acc[nt][2] + acc[nt][3] * acc[nt][3];
            }
            ssq0 += __shfl_xor_sync(0xffffffffu, ssq0, 1);
            ssq0 += __shfl_xor_sync(0xffffffffu, ssq0, 2);
            ssq1 += __shfl_xor_sync(0xffffffffu, ssq1, 1);
            ssq1 += __shfl_xor_sync(0xffffffffu, ssq1, 2);
            nrm0 = sqrtf(ssq0);
            nrm1 = sqrtf(ssq1);
            inv0 = 1.0f / (nrm0 + 1e-10f);
            inv1 = 1.0f / (nrm1 + 1e-10f);
        }

        // ---- prefetch next iteration's k toward L2 ----
        if (tt + 1 < ITERS) {
            const char* np = (const char*)(k + (rowbase + ROWS_ITER) * (long)DD);
            #pragma unroll
            for (int pf = 0; pf < 2; ++pf)
                asm volatile("prefetch.global.L2 [%0];"
                             :: "l"(np + (pf * NTHREADS + tid) * 128));
        }

        // ---- epilogue 1: scale*invnorm -> bucketize -> 8-bit indices to smem ----
        {
            const float2* scl2 = (const float2*)(sb + SM_SCL);
            #pragma unroll
            for (int nt = 0; nt < 16; ++nt) {
                float2 sc = scl2[(8 * nt + 2 * t) >> 1];
                float f0 = acc[nt][0] * sc.x * inv0, f1 = acc[nt][1] * sc.y * inv0;
                float f2 = acc[nt][2] * sc.x * inv1, f3 = acc[nt][3] * sc.y * inv1;
                int i0 = 0, i1 = 0, i2 = 0, i3 = 0;
                #pragma unroll
                for (int q = 0; q < 7; ++q) {
                    i0 += (f0 > bn[q]); i1 += (f1 > bn[q]);
                    i2 += (f2 > bn[q]); i3 += (f3 > bn[q]);
                }
                *(uint16_t*)(zi + rA * 132 + 8 * nt + 2 * t)       = (uint16_t)(i0 | (i1 << 8));
                *(uint16_t*)(zi + (rA + 8) * 132 + 8 * nt + 2 * t) = (uint16_t)(i2 | (i3 << 8));
            }
        }
        __syncwarp();

        // ---- GEMM2 (2-pass tf32): reuse acc registers ----
        #pragma unroll
        for (int nt = 0; nt < 16; ++nt)
            #pragma unroll
            for (int p = 0; p < 4; ++p) acc[nt][p] = 0.0f;

        {
            #pragma unroll 2
            for (int ks = 0; ks < 16; ++ks) {
                float is0 = isclp[8 * ks + t], is1 = isclp[8 * ks + t + 4];
                int sh = 8 * t;
                uint32_t zh[4], zl[4];
                {
                    uint32_t wa = *(const uint32_t*)(zi + rA * 132 + 8 * ks);
                    uint32_t wb = *(const uint32_t*)(zi + rA * 132 + 8 * ks + 4);
                    uint32_t wc = *(const uint32_t*)(zi + (rA + 8) * 132 + 8 * ks);
                    uint32_t wd = *(const uint32_t*)(zi + (rA + 8) * 132 + 8 * ks + 4);
                    float fz[4] = {
                        __shfl_sync(0xffffffffu, ccv, (wa >> sh) & 0xff) * is0,
                        __shfl_sync(0xffffffffu, ccv, (wc >> sh) & 0xff) * is0,
                        __shfl_sync(0xffffffffu, ccv, (wb >> sh) & 0xff) * is1,
                        __shfl_sync(0xffffffffu, ccv, (wd >> sh) & 0xff) * is1 };
                    split4(fz, zh, zl);
                }

                float b0b[2][4], b1b[2][4];
                #pragma unroll
                for (int j = 0; j < 4; ++j) {
                    int base = ((j * 16 + ks) * 32 + t * 4 + (g & 3)) * 2 + (g >> 2);
                    b0b[0][j] = bhf[base];
                    b1b[0][j] = bhf[base + 32];
                }
                #pragma unroll
                for (int grp = 0; grp < 4; ++grp) {
                    const int cur = grp & 1, nxt = cur ^ 1;
                    if (grp < 3) {
                        #pragma unroll
                        for (int j = 0; j < 4; ++j) {
                            int nt2 = (grp + 1) * 4 + j;
                            int base = ((nt2 * 16 + ks) * 32 + t * 4 + (g & 3)) * 2 + (g >> 2);
                            b0b[nxt][j] = bhf[base];
                            b1b[nxt][j] = bhf[base + 32];
                        }
                    }
                    #pragma unroll
                    for (int j = 0; j < 4; ++j) {
                        int nt = grp * 4 + j;
                        uint32_t b0 = __float_as_uint(b0b[cur][j]);
                        uint32_t b1 = __float_as_uint(b1b[cur][j]);
                        mma8(acc[nt], zh, b0, b1);
                        mma8(acc[nt], zl, b0, b1);
                    }
                }
            }
        }

        // ---- epilogue 2: x norm, store ----
        {
            float* o0 = out + (rowbase + rA) * (long)DD;
            float* o1 = o0 + 8 * DD;
            #pragma unroll
            for (int nt = 0; nt < 16; ++nt) {
                int c = 8 * nt + 2 * t;
                *(float2*)(o0 + c) = make_float2(acc[nt][0] * nrm0, acc[nt][1] * nrm0);
                *(float2*)(o1 + c) = make_float2(acc[nt][2] * nrm1, acc[nt][3] * nrm1);
            }
        }
    }
}

extern "C" void kernel_launch(void* const* d_in, const int* in_sizes, int n_in,
                              void* d_out, int out_size) {
    const float* k      = (const float*)d_in[0];
    const float* rot    = (const float*)d_in[1];
    const float* scales = (const float*)d_in[2];
    const float* cent   = (const float*)d_in[3];
    float* out = (float*)d_out;

    int nrows = in_sizes[0] / DD;
    int nblocks = nrows / (ROWS_ITER * ITERS);   // 1048576 / 1024 = 1024

    cudaFuncSetAttribute(rotadapt_mma_kernel,
                         cudaFuncAttributeMaxDynamicSharedMemorySize, SMEM_BYTES);
    rotadapt_mma_kernel<<<nblocks, NTHREADS, SMEM_BYTES>>>(k, rot, scales, cent, out);
}